// round 10
// baseline (speedup 1.0000x reference)
#include <cuda_runtime.h>
#include <math.h>

#define LSEQ 4096
#define PAD2 16             // shifted pad: window starts at t0-16 (16B-aligned loads)
#define TT   8              // t values per block
#define QN   15             // q = t+m range: TT + 7
#define ROW  32             // padded row stride (power of 2)
#define GSTR 68             // G row stride (floats)
#define GHALF (QN * GSTR)   // floats per batch-half
#define BITEMS 240          // 15 q * 8 mp * 2 half

typedef unsigned long long ull;

__device__ __forceinline__ ull mul2(ull a, ull b) {
    ull r; asm("mul.rn.f32x2 %0, %1, %2;" : "=l"(r) : "l"(a), "l"(b)); return r;
}
__device__ __forceinline__ ull fma2(ull a, ull b, ull c) {
    ull r; asm("fma.rn.f32x2 %0, %1, %2, %3;" : "=l"(r) : "l"(a), "l"(b), "l"(c)); return r;
}
union F2U { ull u; float2 f; };

__global__ __launch_bounds__(256, 4)
void gmp_onepass(const float* __restrict__ x,
                 const float* __restrict__ Wr,
                 const float* __restrict__ Wi,
                 float* __restrict__ out) {
    __shared__ float4 tile[32 * ROW];              // (a, a, ur, ui) per (b,pos')
    __shared__ float2 us[32 * ROW];                // (ur, ui) per (b,pos'), 8B stride
    __shared__ __align__(16) float G[2 * GHALF];   // [half][q][mp*8]
    __shared__ float2 Ush[2][QN];                  // per-half U(q)
    __shared__ __align__(16) float2 co_s[TT];      // read back as float4
    __shared__ float  Wsh[2][328];
    __shared__ float2 w0f[8];                      // folded W0'[m]

    const int tid = threadIdx.x;
    const int t0  = blockIdx.x * TT;

    // ---------- Phase A: issue x loads first, then weights ----------------
    // item -> (b, j): one float4 = complex pair at pos' = 2j, 2j+1
    float4 v0 = make_float4(0.f, 0.f, 0.f, 0.f);
    float4 v1 = v0;
    {
        const int b0 = tid >> 4,          j0 = tid & 15;
        const int b1 = (tid + 256) >> 4,  j1 = tid & 15;   // second half: b = b0+16
        const int xa = t0 - PAD2 + 2 * j0;
        // xa even, xa+1 <= LSEQ-1 iff xa <= LSEQ-2
        if (xa >= 0 && xa < LSEQ - 1) {
            v0 = *reinterpret_cast<const float4*>(x + ((size_t)b0 * LSEQ + xa) * 2);
            v1 = *reinterpret_cast<const float4*>(x + ((size_t)b1 * LSEQ + xa) * 2);
        }
        (void)j1;
    }

#pragma unroll
    for (int i = tid; i < 656; i += 256) {
        if (i < 328) Wsh[0][i] = Wr[i];
        else         Wsh[1][i - 328] = Wi[i - 328];
    }
    if (tid < 8) {                                  // W0'[m] = W[m,0] + sum_mp W[m,1+5mp+1]
        const float* wr = Wr + tid * 41;
        const float* wi = Wi + tid * 41;
        float ar = wr[0], ai = wi[0];
#pragma unroll
        for (int mp = 0; mp < 8; ++mp) { ar += wr[2 + 5 * mp]; ai += wi[2 + 5 * mp]; }
        w0f[tid] = make_float2(ar, ai);
    }

    {
        const int b0 = tid >> 4, j = tid & 15;
        float a0 = sqrtf(fmaf(v0.x, v0.x, v0.y * v0.y));
        float a1 = sqrtf(fmaf(v0.z, v0.z, v0.w * v0.w));
        tile[(b0 << 5) + 2 * j]     = make_float4(a0, a0, v0.x, v0.y);
        tile[(b0 << 5) + 2 * j + 1] = make_float4(a1, a1, v0.z, v0.w);
        *reinterpret_cast<float4*>(&us[(b0 << 5) + 2 * j]) = v0;
        const int b1 = b0 + 16;
        float a2 = sqrtf(fmaf(v1.x, v1.x, v1.y * v1.y));
        float a3 = sqrtf(fmaf(v1.z, v1.z, v1.w * v1.w));
        tile[(b1 << 5) + 2 * j]     = make_float4(a2, a2, v1.x, v1.y);
        tile[(b1 << 5) + 2 * j + 1] = make_float4(a3, a3, v1.z, v1.w);
        *reinterpret_cast<float4*>(&us[(b1 << 5) + 2 * j]) = v1;
    }
    __syncthreads();

    // ---------- Phase B: G[h][q][mp] = sum_{b in half h} u[b,q]*ch_d[b,q+mp]
    // pos' = q + 1 (window shifted by one for aligned loads)
    if (tid < BITEMS) {                             // 240/256 threads active
        const int q  = tid % 15;
        const int g  = tid / 15;                    // 0..15
        const int mp = g & 7;
        const int bh = g >> 3;
        const float4* tb = tile + (bh << 9) + q + mp + 1;
        const float2* ub = us   + (bh << 9) + q + 1;
        ull g2 = 0, g3 = 0, g4 = 0;                 // packed (re,im) accumulators
        float g0r = 0.f, g0i = 0.f, usr = 0.f, usi = 0.f;
#pragma unroll 8
        for (int k = 0; k < 16; ++k) {
            ulonglong2 pp = *reinterpret_cast<const ulonglong2*>(tb + (k << 5));
            F2U uq; uq.u = *reinterpret_cast<const ull*>(ub + (k << 5));
            ull aa = pp.x;                          // (a, a) at q+mp
            F2U up; up.u = pp.y;                    // (ur, ui) at q+mp
            ull aa2 = mul2(aa, aa);
            ull aa3 = mul2(aa2, aa);
            g2 = fma2(uq.u, aa,  g2);
            g3 = fma2(uq.u, aa2, g3);
            g4 = fma2(uq.u, aa3, g4);
            g0r = fmaf(uq.f.x,  up.f.x, g0r);
            g0r = fmaf(-uq.f.y, up.f.y, g0r);
            g0i = fmaf(uq.f.x,  up.f.y, g0i);
            g0i = fmaf(uq.f.y,  up.f.x, g0i);
            if (mp == 0) { usr += uq.f.x; usi += uq.f.y; }
        }
        F2U g2f, g3f, g4f; g2f.u = g2; g3f.u = g3; g4f.u = g4;
        float* gq = G + bh * GHALF + q * GSTR + mp * 8;
        *reinterpret_cast<float4*>(gq)     = make_float4(g0r, g0i, g2f.f.x, g2f.f.y);
        *reinterpret_cast<float4*>(gq + 4) = make_float4(g3f.f.x, g3f.f.y, g4f.f.x, g4f.f.y);
        if (mp == 0) Ush[bh][q] = make_float2(usr, usi);
    }
    __syncthreads();

    // ---------- Phase C: co[t] = sum_m sum_mp sum_d c * (G0+G1) -----------
    {
        const int lane = tid & 31;
        const int m    = lane & 7;
        const int g    = lane >> 3;        // 0..3 -> two mp's each
        const int tl   = tid >> 5;         // 0..7
        const int q    = tl + m;
        const float* wr = Wsh[0] + m * 41;
        const float* wi = Wsh[1] + m * 41;

        float accR = 0.f, accI = 0.f;
        if (g == 0) {                      // folded W0'[m] * U(q)
            float2 w0 = w0f[m];
            float2 u0 = Ush[0][q], u1 = Ush[1][q];
            float Ur = u0.x + u1.x, Ui = u0.y + u1.y;
            accR = fmaf(w0.x, Ur, accR); accR = fmaf(-w0.y, Ui, accR);
            accI = fmaf(w0.x, Ui, accI); accI = fmaf(w0.y, Ur, accI);
        }
#pragma unroll
        for (int jj = 0; jj < 2; ++jj) {
            const int mp = g * 2 + jj;
            const float* gq0 = G + q * GSTR + mp * 8;
            const float* gq1 = gq0 + GHALF;
            float4 a0 = *reinterpret_cast<const float4*>(gq0);
            float4 b0 = *reinterpret_cast<const float4*>(gq0 + 4);
            float4 a1 = *reinterpret_cast<const float4*>(gq1);
            float4 b1 = *reinterpret_cast<const float4*>(gq1 + 4);
            float4 gA = make_float4(a0.x + a1.x, a0.y + a1.y, a0.z + a1.z, a0.w + a1.w);
            float4 gB = make_float4(b0.x + b1.x, b0.y + b1.y, b0.z + b1.z, b0.w + b1.w);
            const int o = 1 + 5 * mp;
            float wur = wr[o],     wui = wi[o];
            float c2r = wr[o + 2], c2i = wi[o + 2];
            float c3r = wr[o + 3], c3i = wi[o + 3];
            float c4r = wr[o + 4], c4i = wi[o + 4];
            accR = fmaf(wur,  gA.x, accR); accR = fmaf(-wui, gA.y, accR);
            accI = fmaf(wur,  gA.y, accI); accI = fmaf(wui,  gA.x, accI);
            accR = fmaf(c2r,  gA.z, accR); accR = fmaf(-c2i, gA.w, accR);
            accI = fmaf(c2r,  gA.w, accI); accI = fmaf(c2i,  gA.z, accI);
            accR = fmaf(c3r,  gB.x, accR); accR = fmaf(-c3i, gB.y, accR);
            accI = fmaf(c3r,  gB.y, accI); accI = fmaf(c3i,  gB.x, accI);
            accR = fmaf(c4r,  gB.z, accR); accR = fmaf(-c4i, gB.w, accR);
            accI = fmaf(c4r,  gB.w, accI); accI = fmaf(c4i,  gB.z, accI);
        }
        // full-warp shfl-xor reduction (m bits 0-2, g bits 3-4)
#pragma unroll
        for (int o = 1; o < 32; o <<= 1) {
            accR += __shfl_xor_sync(0xffffffffu, accR, o);
            accI += __shfl_xor_sync(0xffffffffu, accI, o);
        }
        if (lane == 0) co_s[tl] = make_float2(accR, accI);
    }
    __syncthreads();

    // ---------- fused coalesced broadcast: out[b][t0..t0+7] ---------------
    if (tid < 128) {
        const int ob = tid >> 2;           // 0..31
        const int f  = tid & 3;            // 4 float4 = 8 t values
        const float4* c4 = reinterpret_cast<const float4*>(co_s);
        reinterpret_cast<float4*>(out + ((size_t)ob * LSEQ + t0) * 2)[f] = c4[f];
    }
}

extern "C" void kernel_launch(void* const* d_in, const int* in_sizes, int n_in,
                              void* d_out, int out_size) {
    const float* x  = (const float*)d_in[0];
    // d_in[1] = h_0 : unused by the reference computation
    const float* Wr = (const float*)d_in[2];
    const float* Wi = (const float*)d_in[3];

    gmp_onepass<<<LSEQ / TT, 256>>>(x, Wr, Wi, (float*)d_out);
}

// round 11
// speedup vs baseline: 1.2007x; 1.2007x over previous
#include <cuda_runtime.h>
#include <math.h>

#define LSEQ 4096
#define PAD2 16             // shifted pad: window starts at t0-16 (16B-aligned loads)
#define TT   16             // t values per block
#define QN   23             // q = t+m range: TT + 7
#define ROW  32             // padded row stride (power of 2)
#define GSTR 68             // G row stride (floats)
#define GHALF (QN * GSTR)   // floats per batch-half
#define BITEMS 368          // 23 q * 8 mp * 2 half

typedef unsigned long long ull;

__device__ __forceinline__ ull mul2(ull a, ull b) {
    ull r; asm("mul.rn.f32x2 %0, %1, %2;" : "=l"(r) : "l"(a), "l"(b)); return r;
}
__device__ __forceinline__ ull fma2(ull a, ull b, ull c) {
    ull r; asm("fma.rn.f32x2 %0, %1, %2, %3;" : "=l"(r) : "l"(a), "l"(b), "l"(c)); return r;
}
union F2U { ull u; float2 f; };

__global__ __launch_bounds__(512, 3)
void gmp_onepass(const float* __restrict__ x,
                 const float* __restrict__ Wr,
                 const float* __restrict__ Wi,
                 float* __restrict__ out) {
    __shared__ float4 tile[32 * ROW];              // (a, a, ur, ui) per (b,pos')
    __shared__ float2 us[32 * ROW];                // (ur, ui) per (b,pos'), 8B stride
    __shared__ __align__(16) float G[2 * GHALF];   // [half][q][mp*8]
    __shared__ float2 Ush[2][QN];                  // per-half U(q)
    __shared__ __align__(16) float2 co_s[TT];      // read back as float4
    __shared__ float  Wsh[2][328];
    __shared__ float2 w0f[8];                      // folded W0'[m]

    const int tid = threadIdx.x;
    const int t0  = blockIdx.x * TT;

    // ---------- Phase A: issue x load first, then weights -----------------
    // thread -> (b, j): one float4 = complex pair at pos' = 2j, 2j+1
    const int b  = tid >> 4;
    const int j  = tid & 15;
    const int xi0 = t0 - PAD2 + 2 * j;             // 16B-aligned, covers xi0, xi0+1
    float4 v = make_float4(0.f, 0.f, 0.f, 0.f);
    if (xi0 >= 0)                                   // xi0<0 => both elems in zero-pad
        v = *reinterpret_cast<const float4*>(x + ((size_t)b * LSEQ + xi0) * 2);

#pragma unroll
    for (int i = tid; i < 656; i += 512) {
        if (i < 328) Wsh[0][i] = Wr[i];
        else         Wsh[1][i - 328] = Wi[i - 328];
    }
    if (tid < 8) {                                  // W0'[m] = W[m,0] + sum_mp W[m,1+5mp+1]
        const float* wr = Wr + tid * 41;
        const float* wi = Wi + tid * 41;
        float ar = wr[0], ai = wi[0];
#pragma unroll
        for (int mp = 0; mp < 8; ++mp) { ar += wr[2 + 5 * mp]; ai += wi[2 + 5 * mp]; }
        w0f[tid] = make_float2(ar, ai);
    }

    {
        float a0 = sqrtf(fmaf(v.x, v.x, v.y * v.y));
        float a1 = sqrtf(fmaf(v.z, v.z, v.w * v.w));
        tile[(b << 5) + 2 * j]     = make_float4(a0, a0, v.x, v.y);
        tile[(b << 5) + 2 * j + 1] = make_float4(a1, a1, v.z, v.w);
        *reinterpret_cast<float4*>(&us[(b << 5) + 2 * j]) = v;   // two float2 at once
    }
    __syncthreads();

    // ---------- Phase B: G[h][q][mp] = sum_{b in half h} u[b,q]*ch_d[b,q+mp]
    // pos' = old pos + 1  (window shifted by one)
    if (tid < BITEMS) {                             // warps 12-15 skip entirely
        const int q  = tid % 23;
        const int g  = tid / 23;                    // 0..15
        const int mp = g & 7;
        const int bh = g >> 3;
        const float4* tb = tile + (bh << 9) + q + mp + 1;
        const float2* ub = us   + (bh << 9) + q + 1;
        ull g2 = 0, g3 = 0, g4 = 0;                 // packed (re,im) accumulators
        float g0r = 0.f, g0i = 0.f, usr = 0.f, usi = 0.f;
#pragma unroll 8
        for (int k = 0; k < 16; ++k) {
            ulonglong2 pp = *reinterpret_cast<const ulonglong2*>(tb + (k << 5));
            F2U uq; uq.u = *reinterpret_cast<const ull*>(ub + (k << 5));
            ull aa = pp.x;                          // (a, a) at q+mp
            F2U up; up.u = pp.y;                    // (ur, ui) at q+mp
            ull aa2 = mul2(aa, aa);
            ull aa3 = mul2(aa2, aa);
            g2 = fma2(uq.u, aa,  g2);
            g3 = fma2(uq.u, aa2, g3);
            g4 = fma2(uq.u, aa3, g4);
            g0r = fmaf(uq.f.x,  up.f.x, g0r);
            g0r = fmaf(-uq.f.y, up.f.y, g0r);
            g0i = fmaf(uq.f.x,  up.f.y, g0i);
            g0i = fmaf(uq.f.y,  up.f.x, g0i);
            if (mp == 0) { usr += uq.f.x; usi += uq.f.y; }
        }
        F2U g2f, g3f, g4f; g2f.u = g2; g3f.u = g3; g4f.u = g4;
        float* gq = G + bh * GHALF + q * GSTR + mp * 8;
        *reinterpret_cast<float4*>(gq)     = make_float4(g0r, g0i, g2f.f.x, g2f.f.y);
        *reinterpret_cast<float4*>(gq + 4) = make_float4(g3f.f.x, g3f.f.y, g4f.f.x, g4f.f.y);
        if (mp == 0) Ush[bh][q] = make_float2(usr, usi);
    }
    __syncthreads();

    // ---------- Phase C: co[t] = sum_m sum_mp sum_d c * (G0+G1) -----------
    {
        const int lane = tid & 31;
        const int m    = lane & 7;
        const int g    = lane >> 3;        // 0..3 -> two mp's each
        const int tl   = tid >> 5;         // 0..15
        const int q    = tl + m;
        const float* wr = Wsh[0] + m * 41;
        const float* wi = Wsh[1] + m * 41;

        float accR = 0.f, accI = 0.f;
        if (g == 0) {                      // folded W0'[m] * U(q)
            float2 w0 = w0f[m];
            float2 u0 = Ush[0][q], u1 = Ush[1][q];
            float Ur = u0.x + u1.x, Ui = u0.y + u1.y;
            accR = fmaf(w0.x, Ur, accR); accR = fmaf(-w0.y, Ui, accR);
            accI = fmaf(w0.x, Ui, accI); accI = fmaf(w0.y, Ur, accI);
        }
#pragma unroll
        for (int jj = 0; jj < 2; ++jj) {
            const int mp = g * 2 + jj;
            const float* gq0 = G + q * GSTR + mp * 8;
            const float* gq1 = gq0 + GHALF;
            float4 a0 = *reinterpret_cast<const float4*>(gq0);
            float4 b0 = *reinterpret_cast<const float4*>(gq0 + 4);
            float4 a1 = *reinterpret_cast<const float4*>(gq1);
            float4 b1 = *reinterpret_cast<const float4*>(gq1 + 4);
            float4 gA = make_float4(a0.x + a1.x, a0.y + a1.y, a0.z + a1.z, a0.w + a1.w);
            float4 gB = make_float4(b0.x + b1.x, b0.y + b1.y, b0.z + b1.z, b0.w + b1.w);
            const int o = 1 + 5 * mp;
            float wur = wr[o],     wui = wi[o];
            float c2r = wr[o + 2], c2i = wi[o + 2];
            float c3r = wr[o + 3], c3i = wi[o + 3];
            float c4r = wr[o + 4], c4i = wi[o + 4];
            accR = fmaf(wur,  gA.x, accR); accR = fmaf(-wui, gA.y, accR);
            accI = fmaf(wur,  gA.y, accI); accI = fmaf(wui,  gA.x, accI);
            accR = fmaf(c2r,  gA.z, accR); accR = fmaf(-c2i, gA.w, accR);
            accI = fmaf(c2r,  gA.w, accI); accI = fmaf(c2i,  gA.z, accI);
            accR = fmaf(c3r,  gB.x, accR); accR = fmaf(-c3i, gB.y, accR);
            accI = fmaf(c3r,  gB.y, accI); accI = fmaf(c3i,  gB.x, accI);
            accR = fmaf(c4r,  gB.z, accR); accR = fmaf(-c4i, gB.w, accR);
            accI = fmaf(c4r,  gB.w, accI); accI = fmaf(c4i,  gB.z, accI);
        }
        // full-warp shfl-xor reduction (m bits 0-2, g bits 3-4)
#pragma unroll
        for (int o = 1; o < 32; o <<= 1) {
            accR += __shfl_xor_sync(0xffffffffu, accR, o);
            accI += __shfl_xor_sync(0xffffffffu, accI, o);
        }
        if (lane == 0) co_s[tl] = make_float2(accR, accI);
    }
    __syncthreads();

    // ---------- fused coalesced broadcast: out[b][t0..t0+15] --------------
    if (tid < 256) {
        const int ob = tid >> 3;
        const int f  = tid & 7;
        const float4* c4 = reinterpret_cast<const float4*>(co_s);
        reinterpret_cast<float4*>(out + ((size_t)ob * LSEQ + t0) * 2)[f] = c4[f];
    }
}

extern "C" void kernel_launch(void* const* d_in, const int* in_sizes, int n_in,
                              void* d_out, int out_size) {
    const float* x  = (const float*)d_in[0];
    // d_in[1] = h_0 : unused by the reference computation
    const float* Wr = (const float*)d_in[2];
    const float* Wi = (const float*)d_in[3];

    gmp_onepass<<<LSEQ / TT, 512>>>(x, Wr, Wi, (float*)d_out);
}

// round 12
// speedup vs baseline: 1.2362x; 1.0295x over previous
#include <cuda_runtime.h>
#include <math.h>

#define LSEQ 4096
#define PAD2 16             // shifted pad: window starts at t0-16 (16B-aligned loads)
#define TT   16             // t values per block
#define QN   23             // q = t+m range: TT + 7
#define ROW  32             // padded row stride (power of 2)
#define GSTR 68             // G row stride (floats)
#define GHALF (QN * GSTR)   // floats per batch-half
#define BITEMS 368          // 23 q * 8 mp * 2 half
#define UBASE 384           // U-sum items start at warp 12
#define UITEMS 46           // 23 q * 2 half

typedef unsigned long long ull;

__device__ __forceinline__ ull mul2(ull a, ull b) {
    ull r; asm("mul.rn.f32x2 %0, %1, %2;" : "=l"(r) : "l"(a), "l"(b)); return r;
}
__device__ __forceinline__ ull fma2(ull a, ull b, ull c) {
    ull r; asm("fma.rn.f32x2 %0, %1, %2, %3;" : "=l"(r) : "l"(a), "l"(b), "l"(c)); return r;
}
union F2U { ull u; float2 f; };

__global__ __launch_bounds__(512, 2)
void gmp_onepass(const float* __restrict__ x,
                 const float* __restrict__ Wr,
                 const float* __restrict__ Wi,
                 float* __restrict__ out) {
    __shared__ float4 tile[32 * ROW];              // (a, a, ur, ui) per (b,pos')
    __shared__ float2 us[32 * ROW];                // (ur, ui) per (b,pos'), 8B stride
    __shared__ __align__(16) float G[2 * GHALF];   // [half][q][mp*8]
    __shared__ float2 Ush[2][QN];                  // per-half U(q)
    __shared__ __align__(16) float2 co_s[TT];      // read back as float4
    __shared__ float  Wsh[2][328];
    __shared__ float2 w0f[8];                      // folded W0'[m]

    const int tid = threadIdx.x;
    const int t0  = blockIdx.x * TT;

    // ---------- Phase A: issue x load first, then weights -----------------
    // thread -> (b, j): one float4 = complex pair at pos' = 2j, 2j+1
    const int b  = tid >> 4;
    const int j  = tid & 15;
    const int xi0 = t0 - PAD2 + 2 * j;             // 16B-aligned, covers xi0, xi0+1
    float4 v = make_float4(0.f, 0.f, 0.f, 0.f);
    if (xi0 >= 0)                                   // xi0<0 => both elems in zero-pad
        v = *reinterpret_cast<const float4*>(x + ((size_t)b * LSEQ + xi0) * 2);

#pragma unroll
    for (int i = tid; i < 656; i += 512) {
        if (i < 328) Wsh[0][i] = Wr[i];
        else         Wsh[1][i - 328] = Wi[i - 328];
    }
    if (tid < 8) {                                  // W0'[m] = W[m,0] + sum_mp W[m,1+5mp+1]
        const float* wr = Wr + tid * 41;
        const float* wi = Wi + tid * 41;
        float ar = wr[0], ai = wi[0];
#pragma unroll
        for (int mp = 0; mp < 8; ++mp) { ar += wr[2 + 5 * mp]; ai += wi[2 + 5 * mp]; }
        w0f[tid] = make_float2(ar, ai);
    }

    {
        float a0 = sqrtf(fmaf(v.x, v.x, v.y * v.y));
        float a1 = sqrtf(fmaf(v.z, v.z, v.w * v.w));
        tile[(b << 5) + 2 * j]     = make_float4(a0, a0, v.x, v.y);
        tile[(b << 5) + 2 * j + 1] = make_float4(a1, a1, v.z, v.w);
        *reinterpret_cast<float4*>(&us[(b << 5) + 2 * j]) = v;   // two float2 at once
    }
    __syncthreads();

    // ---------- Phase B: G[h][q][mp] = sum_{b in half h} u[b,q]*ch_d[b,q+mp]
    // pos' = q + 1  (window shifted by one for aligned A-loads)
    if (tid < BITEMS) {                             // warps 0-11 (368 threads)
        const int q  = tid % 23;
        const int g  = tid / 23;                    // 0..15
        const int mp = g & 7;
        const int bh = g >> 3;
        const float4* tb = tile + (bh << 9) + q + mp + 1;
        const float2* ub = us   + (bh << 9) + q + 1;
        ull g2 = 0, g3 = 0, g4 = 0;                 // packed (re,im) accumulators
        float g0r = 0.f, g0i = 0.f;
#pragma unroll 8
        for (int k = 0; k < 16; ++k) {
            ulonglong2 pp = *reinterpret_cast<const ulonglong2*>(tb + (k << 5));
            F2U uq; uq.u = *reinterpret_cast<const ull*>(ub + (k << 5));
            ull aa = pp.x;                          // (a, a) at q+mp
            F2U up; up.u = pp.y;                    // (ur, ui) at q+mp
            ull aa2 = mul2(aa, aa);
            ull aa3 = mul2(aa2, aa);
            g2 = fma2(uq.u, aa,  g2);
            g3 = fma2(uq.u, aa2, g3);
            g4 = fma2(uq.u, aa3, g4);
            g0r = fmaf(uq.f.x,  up.f.x, g0r);
            g0r = fmaf(-uq.f.y, up.f.y, g0r);
            g0i = fmaf(uq.f.x,  up.f.y, g0i);
            g0i = fmaf(uq.f.y,  up.f.x, g0i);
        }
        F2U g2f, g3f, g4f; g2f.u = g2; g3f.u = g3; g4f.u = g4;
        float* gq = G + bh * GHALF + q * GSTR + mp * 8;
        *reinterpret_cast<float4*>(gq)     = make_float4(g0r, g0i, g2f.f.x, g2f.f.y);
        *reinterpret_cast<float4*>(gq + 4) = make_float4(g3f.f.x, g3f.f.y, g4f.f.x, g4f.f.y);
    } else if (tid >= UBASE && tid < UBASE + UITEMS) {
        // U(q) per batch-half, computed by otherwise-idle warps 12-13
        const int it = tid - UBASE;
        const int q  = it % 23;
        const int bh = it / 23;
        const float2* ub = us + (bh << 9) + q + 1;
        float usr = 0.f, usi = 0.f;
#pragma unroll 8
        for (int k = 0; k < 16; ++k) {
            F2U uq; uq.u = *reinterpret_cast<const ull*>(ub + (k << 5));
            usr += uq.f.x; usi += uq.f.y;
        }
        Ush[bh][q] = make_float2(usr, usi);
    }
    __syncthreads();

    // ---------- Phase C: co[t] = sum_m sum_mp sum_d c * (G0+G1) -----------
    {
        const int lane = tid & 31;
        const int m    = lane & 7;
        const int g    = lane >> 3;        // 0..3 -> two mp's each
        const int tl   = tid >> 5;         // 0..15
        const int q    = tl + m;
        const float* wr = Wsh[0] + m * 41;
        const float* wi = Wsh[1] + m * 41;

        float accR = 0.f, accI = 0.f;
        if (g == 0) {                      // folded W0'[m] * U(q)
            float2 w0 = w0f[m];
            float2 u0 = Ush[0][q], u1 = Ush[1][q];
            float Ur = u0.x + u1.x, Ui = u0.y + u1.y;
            accR = fmaf(w0.x, Ur, accR); accR = fmaf(-w0.y, Ui, accR);
            accI = fmaf(w0.x, Ui, accI); accI = fmaf(w0.y, Ur, accI);
        }
#pragma unroll
        for (int jj = 0; jj < 2; ++jj) {
            const int mp = g * 2 + jj;
            const float* gq0 = G + q * GSTR + mp * 8;
            const float* gq1 = gq0 + GHALF;
            float4 a0 = *reinterpret_cast<const float4*>(gq0);
            float4 b0 = *reinterpret_cast<const float4*>(gq0 + 4);
            float4 a1 = *reinterpret_cast<const float4*>(gq1);
            float4 b1 = *reinterpret_cast<const float4*>(gq1 + 4);
            float4 gA = make_float4(a0.x + a1.x, a0.y + a1.y, a0.z + a1.z, a0.w + a1.w);
            float4 gB = make_float4(b0.x + b1.x, b0.y + b1.y, b0.z + b1.z, b0.w + b1.w);
            const int o = 1 + 5 * mp;
            float wur = wr[o],     wui = wi[o];
            float c2r = wr[o + 2], c2i = wi[o + 2];
            float c3r = wr[o + 3], c3i = wi[o + 3];
            float c4r = wr[o + 4], c4i = wi[o + 4];
            accR = fmaf(wur,  gA.x, accR); accR = fmaf(-wui, gA.y, accR);
            accI = fmaf(wur,  gA.y, accI); accI = fmaf(wui,  gA.x, accI);
            accR = fmaf(c2r,  gA.z, accR); accR = fmaf(-c2i, gA.w, accR);
            accI = fmaf(c2r,  gA.w, accI); accI = fmaf(c2i,  gA.z, accI);
            accR = fmaf(c3r,  gB.x, accR); accR = fmaf(-c3i, gB.y, accR);
            accI = fmaf(c3r,  gB.y, accI); accI = fmaf(c3i,  gB.x, accI);
            accR = fmaf(c4r,  gB.z, accR); accR = fmaf(-c4i, gB.w, accR);
            accI = fmaf(c4r,  gB.w, accI); accI = fmaf(c4i,  gB.z, accI);
        }
        // full-warp shfl-xor reduction (m bits 0-2, g bits 3-4)
#pragma unroll
        for (int o = 1; o < 32; o <<= 1) {
            accR += __shfl_xor_sync(0xffffffffu, accR, o);
            accI += __shfl_xor_sync(0xffffffffu, accI, o);
        }
        if (lane == 0) co_s[tl] = make_float2(accR, accI);
    }
    __syncthreads();

    // ---------- fused coalesced broadcast: out[b][t0..t0+15] --------------
    if (tid < 256) {
        const int ob = tid >> 3;
        const int f  = tid & 7;
        const float4* c4 = reinterpret_cast<const float4*>(co_s);
        reinterpret_cast<float4*>(out + ((size_t)ob * LSEQ + t0) * 2)[f] = c4[f];
    }
}

extern "C" void kernel_launch(void* const* d_in, const int* in_sizes, int n_in,
                              void* d_out, int out_size) {
    const float* x  = (const float*)d_in[0];
    // d_in[1] = h_0 : unused by the reference computation
    const float* Wr = (const float*)d_in[2];
    const float* Wi = (const float*)d_in[3];

    gmp_onepass<<<LSEQ / TT, 512>>>(x, Wr, Wi, (float*)d_out);
}